// round 10
// baseline (speedup 1.0000x reference)
#include <cuda_runtime.h>
#include <math.h>

#define BATCH 8
#define SEQL  4096
#define DM    256
#define HH    768
#define NST   32
#define TCH   64
#define NC    (SEQL/TCH)   // 64

// ---------------- scratch (static device globals; no allocation) ----------------
__device__ float g_gate [(size_t)BATCH*HH*SEQL];   // sigmoid(gate) TRANSPOSED [b][h][l]
__device__ float g_resid[(size_t)BATCH*SEQL*HH];   // [b][l][h]
__device__ float g_gated[(size_t)BATCH*HH*SEQL];   // [b][h][l]
__device__ float g_ys4  [(size_t)BATCH*HH*SEQL];   // [b][h][l]
__device__ float g_xp   [(size_t)BATCH*SEQL*DM];   // x, tf32-rounded
__device__ float g_Wp   [2*HH*DM];                 // gate|res weights, tf32-rounded
__device__ float g_Wt   [25*DM*DM];                // [tap][o][c], tf32-rounded
__device__ float g_kern [HH*TCH];
__device__ float g_E    [HH*TCH*NST*2];
__device__ float g_P    [HH*TCH*NST*2];
__device__ float g_lamT [HH*NST*2];
__device__ float g_S    [(size_t)BATCH*HH*NC*NST*2];   // [bh][c][64nri]
__device__ float g_Pm   [(size_t)HH*TCH*TCH];
__device__ float g_Tm   [(size_t)HH*TCH*TCH];
__device__ float g_Dm   [(size_t)HH*TCH*TCH];

__device__ __forceinline__ unsigned f2tf(float f) {
    unsigned u; asm("cvt.rna.tf32.f32 %0, %1;" : "=r"(u) : "f"(f)); return u;
}
__device__ __forceinline__ void mma_tf32(float c[4], const unsigned a[4], const unsigned b[2]) {
    asm volatile("mma.sync.aligned.m16n8k8.row.col.f32.tf32.tf32.f32 "
        "{%0,%1,%2,%3}, {%4,%5,%6,%7}, {%8,%9}, {%0,%1,%2,%3};"
        : "+f"(c[0]), "+f"(c[1]), "+f"(c[2]), "+f"(c[3])
        : "r"(a[0]), "r"(a[1]), "r"(a[2]), "r"(a[3]), "r"(b[0]), "r"(b[1]));
}

// ---------------- K0a: x -> g_xp (tf32-rounded) ----------------
__global__ void k_xp(const float* __restrict__ x) {
    size_t i = (size_t)blockIdx.x*256 + threadIdx.x;
    g_xp[i] = __uint_as_float(f2tf(x[i]));
}
// ---------------- K0b: gate/res weights -> g_Wp ----------------
__global__ void k_wp(const float* __restrict__ gw, const float* __restrict__ rw) {
    int o = blockIdx.x, c = threadIdx.x;
    float v = (o < HH) ? gw[(size_t)o*DM + c] : rw[(size_t)(o-HH)*DM + c];
    g_Wp[(size_t)o*DM + c] = __uint_as_float(f2tf(v));
}
// ---------------- K0c: conv weights -> [tap][o][c], tf32 ----------------
__global__ void k_wt(const float* __restrict__ w0, const float* __restrict__ w1,
                     const float* __restrict__ w2) {
    int idx = blockIdx.x * 256 + threadIdx.x;       // tap<<16 | o<<8 | c
    int c = idx & 255, o = (idx >> 8) & 255, tap = idx >> 16;
    const float* w; int k, K;
    if (tap < 3)       { w = w0; k = tap;      K = 3;  }
    else if (tap < 10) { w = w1; k = tap - 3;  K = 7;  }
    else               { w = w2; k = tap - 10; K = 15; }
    g_Wt[idx] = __uint_as_float(f2tf(w[(o * DM + c) * K + k]));
}

// ---------------- K0d: S4D parameter tables ----------------
__global__ void k_s4prep(const float* __restrict__ log_dt, const float* __restrict__ A_re,
                         const float* __restrict__ A_im,  const float* __restrict__ C_re,
                         const float* __restrict__ C_im) {
    int h = blockIdx.x, n = threadIdx.x;
    float dt  = expf(log_dt[h]);
    float ar  = A_re[h*NST+n], ai = A_im[h*NST+n];
    float dar = dt*ar, dai = dt*ai;
    float er  = expf(dar);
    float lr  = er*cosf(dai), li = er*sinf(dai);
    float nr  = lr - 1.f, ni = li;
    float cr  = C_re[h*NST+n], ci = C_im[h*NST+n];
    float t1r = cr*nr - ci*ni, t1i = cr*ni + ci*nr;
    float den = ar*ar + ai*ai;
    float cdr = (t1r*ar + t1i*ai)/den;
    float cdi = (t1i*ar - t1r*ai)/den;

    float pr = cdr, pi = cdi;
    for (int t = 0; t < TCH; t++) {
        float s = pr;
        #pragma unroll
        for (int off = 16; off; off >>= 1) s += __shfl_xor_sync(0xffffffffu, s, off);
        if (n == 0) g_kern[h*TCH + t] = 2.f*s;
        float npr = pr*lr - pi*li, npi = pr*li + pi*lr;
        pr = npr; pi = npi;
        g_E[((h*TCH + t)*NST + n)*2 + 0] = pr;
        g_E[((h*TCH + t)*NST + n)*2 + 1] = pi;
    }
    float qr = 1.f, qi = 0.f;
    for (int m = 0; m < TCH; m++) {
        g_P[((h*TCH + (TCH-1-m))*NST + n)*2 + 0] = qr;
        g_P[((h*TCH + (TCH-1-m))*NST + n)*2 + 1] = qi;
        float nqr = qr*lr - qi*li, nqi = qr*li + qi*lr;
        qr = nqr; qi = nqi;
    }
    g_lamT[(h*NST+n)*2+0] = qr;
    g_lamT[(h*NST+n)*2+1] = qi;
}

// ---------------- K0e: GEMM-layout tables Pm/Tm/Dm ----------------
__global__ void k_tables(const float* __restrict__ Dskip) {
    int h = blockIdx.x;
    float dsk = Dskip[h];
    for (int i = threadIdx.x; i < TCH*TCH; i += 256) {
        int nri = i >> 6, t = i & 63;
        int n = nri >> 1, ri = nri & 1;
        g_Pm[(size_t)h*4096 + i] = __uint_as_float(f2tf(g_P[((h*TCH + t)*NST + n)*2 + ri]));
        int to = i >> 6, nri2 = i & 63;
        int n2 = nri2 >> 1, ri2 = nri2 & 1;
        float e = g_E[((h*TCH + to)*NST + n2)*2 + ri2];
        g_Dm[(size_t)h*4096 + i] = __uint_as_float(f2tf(ri2 ? -2.f*e : 2.f*e));
        int ti = i & 63;
        float v = 0.f;
        if (to >= ti) { v = g_kern[h*TCH + (to - ti)]; if (to == ti) v += dsk; }
        g_Tm[(size_t)h*4096 + i] = __uint_as_float(f2tf(v));
    }
}

// ---------------- K1: gate + res projections (block 64x128, warp m16n64, 3 CTA/SM) ----------------
__global__ __launch_bounds__(256, 3) void k_gemm(const float* __restrict__ gb,
                                                 const float* __restrict__ rb) {
    extern __shared__ unsigned sm[];
    unsigned* Xs = sm;              // [64][68]
    unsigned* Ws = sm + 64*68;      // [128][68]
    int row0 = blockIdx.x * 64;
    int col0 = blockIdx.y * 128;
    int z    = blockIdx.z;
    const unsigned* Xp = (const unsigned*)g_xp;
    const unsigned* Wp = (const unsigned*)g_Wp + (z ? (size_t)HH*DM : 0);
    const float* Bv = z ? rb : gb;
    int tid = threadIdx.x, lane = tid & 31, wp = tid >> 5;
    int mw = (wp & 3) * 16, nw = (wp >> 2) * 64;
    int r_lo = lane >> 2, tg = lane & 3;
    float acc[8][4] = {};
    for (int c0 = 0; c0 < DM; c0 += 64) {
        __syncthreads();
        #pragma unroll
        for (int i = 0; i < 4; i++) {
            int lin = i*256 + tid; int r = lin >> 4, q = lin & 15;
            *(uint4*)(Xs + r*68 + 4*q) = *(const uint4*)(Xp + (size_t)(row0 + r)*DM + c0 + 4*q);
        }
        #pragma unroll
        for (int i = 0; i < 8; i++) {
            int lin = i*256 + tid; int r = lin >> 4, q = lin & 15;
            *(uint4*)(Ws + r*68 + 4*q) = *(const uint4*)(Wp + (size_t)(col0 + r)*DM + c0 + 4*q);
        }
        __syncthreads();
        #pragma unroll
        for (int kk = 0; kk < 64; kk += 8) {
            unsigned a[4], b[8][2];
            int base = (mw + r_lo)*68 + kk + tg;
            a[0] = Xs[base];       a[1] = Xs[base + 8*68];
            a[2] = Xs[base + 4];   a[3] = Xs[base + 8*68 + 4];
            #pragma unroll
            for (int nt = 0; nt < 8; nt++) {
                int bb = (nw + nt*8 + r_lo)*68 + kk + tg;
                b[nt][0] = Ws[bb]; b[nt][1] = Ws[bb + 4];
            }
            #pragma unroll
            for (int nt = 0; nt < 8; nt++)
                mma_tf32(acc[nt], a, b[nt]);
        }
    }
    if (z == 1) {   // residual: direct [b*l][h]
        #pragma unroll
        for (int nt = 0; nt < 8; nt++)
            #pragma unroll
            for (int rr = 0; rr < 2; rr++) {
                int row = row0 + mw + r_lo + rr*8;
                int col = col0 + nw + nt*8 + 2*tg;
                float2 v = make_float2(acc[nt][rr*2+0] + Bv[col],
                                       acc[nt][rr*2+1] + Bv[col+1]);
                *(float2*)(g_resid + (size_t)row*HH + col) = v;
            }
    } else {        // gate: sigmoid + transpose-stage -> g_gate[b][h][l]
        __syncthreads();
        float* tile = (float*)sm;   // [128 h][68 l]
        #pragma unroll
        for (int nt = 0; nt < 8; nt++)
            #pragma unroll
            for (int rr = 0; rr < 2; rr++) {
                int m = mw + r_lo + rr*8;
                int n = nw + nt*8 + 2*tg;
                float v0 = acc[nt][rr*2+0] + Bv[col0+n];
                float v1 = acc[nt][rr*2+1] + Bv[col0+n+1];
                tile[n*68 + m]     = 1.f/(1.f + __expf(-v0));
                tile[(n+1)*68 + m] = 1.f/(1.f + __expf(-v1));
            }
        __syncthreads();
        int b = row0 / SEQL, l0 = row0 % SEQL;
        int hh = tid >> 1, l_off = (tid & 1) * 32;
        float* dst = g_gate + ((size_t)(b*HH) + col0 + hh)*SEQL + l0 + l_off;
        #pragma unroll
        for (int q = 0; q < 8; q++)
            *(float4*)(dst + 4*q) = *(float4*)(tile + hh*68 + l_off + 4*q);
    }
}

// ---------------- K2: dilated convs (block 64l x 128o, warp m16n64, 3 CTA/SM) ----------------
__global__ __launch_bounds__(256, 3) void k_conv(const float* __restrict__ cb0,
        const float* __restrict__ cb1, const float* __restrict__ cb2) {
    extern __shared__ unsigned sm[];
    unsigned* Us = sm;                // [120][68]  (halo -28..+91)
    unsigned* Ws = sm + 120*68;       // [128 o][68 c]
    int br   = blockIdx.y >> 1;
    int o0   = (blockIdx.y & 1) * 128;
    int K, dil, tb; const float* cb;
    if (br == 0)      { K = 3;  dil = 1; tb = 0;  cb = cb0; }
    else if (br == 1) { K = 7;  dil = 2; tb = 3;  cb = cb1; }
    else              { K = 15; dil = 4; tb = 10; cb = cb2; }
    int l0 = blockIdx.x * 64;
    int b  = blockIdx.z;
    int tid = threadIdx.x, lane = tid & 31, wp = tid >> 5;
    int mw = (wp & 3) * 16, nw = (wp >> 2) * 64;
    int r_lo = lane >> 2, tg = lane & 3;
    float acc[8][4] = {};
    const unsigned* Xp  = (const unsigned*)g_xp;
    const unsigned* Wtu = (const unsigned*)g_Wt;
    for (int c0 = 0; c0 < DM; c0 += 64) {
        __syncthreads();
        #pragma unroll
        for (int i = 0; i < 8; i++) {
            int lin = i*256 + tid;
            if (lin < 1920) {
                int r = lin >> 4, q = lin & 15;
                int l = l0 - 28 + r;
                uint4 t = make_uint4(0u, 0u, 0u, 0u);
                if ((unsigned)l < SEQL)
                    t = *(const uint4*)(Xp + ((size_t)(b*SEQL + l))*DM + c0 + 4*q);
                *(uint4*)(Us + r*68 + 4*q) = t;
            }
        }
        for (int k = 0; k < K; k++) {
            __syncthreads();
            #pragma unroll
            for (int i = 0; i < 8; i++) {
                int lin = i*256 + tid; int r = lin >> 4, q = lin & 15;
                *(uint4*)(Ws + r*68 + 4*q) =
                    *(const uint4*)(Wtu + (size_t)(tb + k)*65536 + (o0 + r)*256 + c0 + 4*q);
            }
            __syncthreads();
            int lb = 28 + (k - K/2) * dil;
            #pragma unroll
            for (int kk = 0; kk < 64; kk += 8) {
                unsigned a[4], bfr[8][2];
                int base = (lb + mw + r_lo)*68 + kk + tg;
                a[0] = Us[base];       a[1] = Us[base + 8*68];
                a[2] = Us[base + 4];   a[3] = Us[base + 8*68 + 4];
                #pragma unroll
                for (int nt = 0; nt < 8; nt++) {
                    int bb = (nw + nt*8 + r_lo)*68 + kk + tg;
                    bfr[nt][0] = Ws[bb]; bfr[nt][1] = Ws[bb + 4];
                }
                #pragma unroll
                for (int nt = 0; nt < 8; nt++)
                    mma_tf32(acc[nt], a, bfr[nt]);
            }
        }
    }
    __syncthreads();
    float* tile = (float*)sm;   // [128 o][68 l]
    #pragma unroll
    for (int nt = 0; nt < 8; nt++)
        #pragma unroll
        for (int rr = 0; rr < 2; rr++) {
            int m = mw + r_lo + rr*8;
            int n = nw + nt*8 + 2*tg;
            tile[n*68 + m]     = acc[nt][rr*2+0];
            tile[(n+1)*68 + m] = acc[nt][rr*2+1];
        }
    __syncthreads();
    int hh = tid >> 1, l_off = (tid & 1) * 32;
    int hglob = br*256 + o0 + hh;
    float bias = cb[o0 + hh];
    const float* gp = g_gate  + ((size_t)(b*HH) + hglob)*SEQL + l0 + l_off;
    float*       op = g_gated + ((size_t)(b*HH) + hglob)*SEQL + l0 + l_off;
    #pragma unroll
    for (int q = 0; q < 8; q++) {
        float4 a = *(float4*)(tile + hh*68 + l_off + 4*q);
        float4 g = *(const float4*)(gp + 4*q);
        *(float4*)(op + 4*q) = make_float4((a.x+bias)*g.x, (a.y+bias)*g.y,
                                           (a.z+bias)*g.z, (a.w+bias)*g.w);
    }
}

// ---------------- 64x64x64 tf32 GEMM helpers ----------------
__device__ __forceinline__ void load_tile_tf32(unsigned* dst, const float* src, int tid) {
    const float4* p = (const float4*)src;
    #pragma unroll
    for (int i = 0; i < 8; i++) {
        int lin = i*128 + tid; int r = lin >> 4, q = lin & 15;
        float4 v = p[lin];
        *(uint4*)(dst + r*68 + 4*q) = make_uint4(f2tf(v.x), f2tf(v.y), f2tf(v.z), f2tf(v.w));
    }
}
__device__ __forceinline__ void load_tile_raw(unsigned* dst, const unsigned* src, int tid) {
    const uint4* p = (const uint4*)src;
    #pragma unroll
    for (int i = 0; i < 8; i++) {
        int lin = i*128 + tid; int r = lin >> 4, q = lin & 15;
        *(uint4*)(dst + r*68 + 4*q) = p[lin];
    }
}
__device__ __forceinline__ void gemm64(float acc[8][4], const unsigned* As, const unsigned* Bs,
                                       int m0, int r_lo, int tg) {
    #pragma unroll
    for (int kk = 0; kk < 64; kk += 8) {
        unsigned a[4];
        int base = (m0 + r_lo)*68 + kk + tg;
        a[0] = As[base];       a[1] = As[base + 8*68];
        a[2] = As[base + 4];   a[3] = As[base + 8*68 + 4];
        #pragma unroll
        for (int nt = 0; nt < 8; nt++) {
            unsigned b[2]; int bb = (nt*8 + r_lo)*68 + kk + tg;
            b[0] = Bs[bb]; b[1] = Bs[bb + 4];
            mma_tf32(acc[nt], a, b);
        }
    }
}

// ---------------- K3: encode + in-block cross-chunk scan -> g_S ----------------
__global__ __launch_bounds__(128) void k_enc(void) {
    __shared__ unsigned Us[64*68], Ps[64*68];
    int bh = blockIdx.x, h = bh % HH, tid = threadIdx.x;
    load_tile_tf32(Us, g_gated + (size_t)bh*SEQL, tid);
    load_tile_raw (Ps, (const unsigned*)g_Pm + (size_t)h*4096, tid);
    __syncthreads();
    int lane = tid & 31, wp = tid >> 5, m0 = wp*16, r_lo = lane >> 2, tg = lane & 3;
    float acc[8][4] = {};
    gemm64(acc, Us, Ps, m0, r_lo, tg);
    __syncthreads();                       // all warps done reading Ps
    float* Fs = (float*)Ps;                // reuse as F[64 chunks][64 nri]
    #pragma unroll
    for (int nt = 0; nt < 8; nt++) {
        int col = nt*8 + 2*tg;
        Fs[(m0 + r_lo)*64 + col]       = acc[nt][0];
        Fs[(m0 + r_lo)*64 + col + 1]   = acc[nt][1];
        Fs[(m0 + r_lo + 8)*64 + col]   = acc[nt][2];
        Fs[(m0 + r_lo + 8)*64 + col+1] = acc[nt][3];
    }
    __syncthreads();
    if (tid < 32) {                        // warp 0: sequential scan over 64 chunks
        int n = tid;
        float2 lam = ((const float2*)g_lamT)[h*NST + n];
        float sr = 0.f, si = 0.f;
        float2* S2 = (float2*)(g_S + (size_t)bh*4096);
        for (int c = 0; c < NC; c++) {
            S2[c*32 + n] = make_float2(sr, si);
            float2 f = *(float2*)(Fs + c*64 + 2*n);
            float nsr = sr*lam.x - si*lam.y + f.x;
            float nsi = sr*lam.y + si*lam.x + f.y;
            sr = nsr; si = nsi;
        }
    }
}

// ---------------- K5: decode Y = U*Tm^T + S*Dm^T -> g_ys4 ----------------
__global__ __launch_bounds__(128) void k_dec(void) {
    __shared__ unsigned As[64*68], Bs[64*68];
    int bh = blockIdx.x, h = bh % HH, tid = threadIdx.x;
    load_tile_tf32(As, g_gated + (size_t)bh*SEQL, tid);
    load_tile_raw (Bs, (const unsigned*)g_Tm + (size_t)h*4096, tid);
    __syncthreads();
    int lane = tid & 31, wp = tid >> 5, m0 = wp*16, r_lo = lane >> 2, tg = lane & 3;
    float acc[8][4] = {};
    gemm64(acc, As, Bs, m0, r_lo, tg);
    __syncthreads();
    load_tile_tf32(As, g_S + (size_t)bh*4096, tid);
    load_tile_raw (Bs, (const unsigned*)g_Dm + (size_t)h*4096, tid);
    __syncthreads();
    gemm64(acc, As, Bs, m0, r_lo, tg);
    #pragma unroll
    for (int nt = 0; nt < 8; nt++) {
        int col = nt*8 + 2*tg;
        float* f = g_ys4 + (size_t)bh*SEQL + (m0 + r_lo)*64 + col;
        *(float2*)f         = make_float2(acc[nt][0], acc[nt][1]);
        *(float2*)(f + 512) = make_float2(acc[nt][2], acc[nt][3]);
    }
}

// ---------------- K6: transpose + residual + LayerNorm ----------------
__global__ __launch_bounds__(256) void k_ln(const float* __restrict__ gamma,
                                            const float* __restrict__ beta,
                                            float* __restrict__ out) {
    __shared__ float tile[16][768];
    int b  = blockIdx.y;
    int l0 = blockIdx.x * 16;
    for (int hh = threadIdx.x; hh < HH; hh += 256) {
        const float4* p = (const float4*)(g_ys4 + ((size_t)(b*HH + hh))*SEQL + l0);
        #pragma unroll
        for (int q = 0; q < 4; q++) {
            float4 v = p[q];
            tile[4*q+0][hh] = v.x; tile[4*q+1][hh] = v.y;
            tile[4*q+2][hh] = v.z; tile[4*q+3][hh] = v.w;
        }
    }
    __syncthreads();
    int w = threadIdx.x >> 5, lane = threadIdx.x & 31;
    #pragma unroll
    for (int rr = 0; rr < 2; rr++) {
        int j = w + rr*8;
        int l = l0 + j;
        size_t rbase = ((size_t)(b*SEQL + l))*HH;
        float s = 0.f, s2 = 0.f;
        for (int hh = lane; hh < HH; hh += 32) {
            float y = tile[j][hh] + g_resid[rbase + hh];
            tile[j][hh] = y;
            s += y; s2 += y*y;
        }
        #pragma unroll
        for (int off = 16; off; off >>= 1) {
            s  += __shfl_xor_sync(0xffffffffu, s,  off);
            s2 += __shfl_xor_sync(0xffffffffu, s2, off);
        }
        float mu   = s * (1.f/HH);
        float var  = s2 * (1.f/HH) - mu*mu;
        float rstd = rsqrtf(var + 1e-5f);
        for (int hh = lane; hh < HH; hh += 32) {
            out[rbase + hh] = (tile[j][hh] - mu) * rstd * gamma[hh] + beta[hh];
        }
    }
}

extern "C" void kernel_launch(void* const* d_in, const int* in_sizes, int n_in,
                              void* d_out, int out_size) {
    const float* x      = (const float*)d_in[0];
    const float* cw0    = (const float*)d_in[1];
    const float* cb0    = (const float*)d_in[2];
    const float* cw1    = (const float*)d_in[3];
    const float* cb1    = (const float*)d_in[4];
    const float* cw2    = (const float*)d_in[5];
    const float* cb2    = (const float*)d_in[6];
    const float* gw     = (const float*)d_in[7];
    const float* gb     = (const float*)d_in[8];
    const float* rw     = (const float*)d_in[9];
    const float* rb     = (const float*)d_in[10];
    const float* log_dt = (const float*)d_in[11];
    const float* A_re   = (const float*)d_in[12];
    const float* A_im   = (const float*)d_in[13];
    const float* C_re   = (const float*)d_in[14];
    const float* C_im   = (const float*)d_in[15];
    const float* Dskip  = (const float*)d_in[16];
    const float* lng    = (const float*)d_in[17];
    const float* lnb    = (const float*)d_in[18];
    float* out = (float*)d_out;

    const int GEMM_SMEM = (64 + 128) * 68 * 4;    // 52224 B  -> 3 CTA/SM
    const int CONV_SMEM = (120 + 128) * 68 * 4;   // 67456 B  -> 3 CTA/SM
    cudaFuncSetAttribute(k_gemm, cudaFuncAttributeMaxDynamicSharedMemorySize, GEMM_SMEM);
    cudaFuncSetAttribute(k_conv, cudaFuncAttributeMaxDynamicSharedMemorySize, CONV_SMEM);

    k_xp<<<(BATCH*SEQL*DM)/256, 256>>>(x);
    k_wp<<<2*HH, 256>>>(gw, rw);
    k_wt<<<25*256, 256>>>(cw0, cw1, cw2);
    k_s4prep<<<HH, NST>>>(log_dt, A_re, A_im, C_re, C_im);
    k_tables<<<HH, 256>>>(Dskip);
    k_gemm<<<dim3(512, 6, 2), 256, GEMM_SMEM>>>(gb, rb);
    k_conv<<<dim3(64, 6, 8), 256, CONV_SMEM>>>(cb0, cb1, cb2);
    k_enc<<<BATCH*HH, 128>>>();
    k_dec<<<BATCH*HH, 128>>>();
    k_ln<<<dim3(SEQL/16, BATCH), 256>>>(lng, lnb, out);
}

// round 14
// speedup vs baseline: 1.1747x; 1.1747x over previous
#include <cuda_runtime.h>
#include <math.h>

#define BATCH 8
#define SEQL  4096
#define DM    256
#define HH    768
#define NST   32
#define TCH   64
#define NC    (SEQL/TCH)   // 64

// ---------------- scratch (static device globals; no allocation) ----------------
__device__ float g_gate [(size_t)BATCH*HH*SEQL];   // sigmoid(gate) TRANSPOSED [b][h][l]
__device__ float g_resid[(size_t)BATCH*SEQL*HH];   // [b][l][h]
__device__ float g_gated[(size_t)BATCH*HH*SEQL];   // [b][h][l]
__device__ float g_ys4  [(size_t)BATCH*HH*SEQL];   // [b][h][l]
__device__ float g_xp   [(size_t)BATCH*SEQL*DM];   // x, tf32-rounded
__device__ float g_Wp   [2*HH*DM];                 // gate|res weights, tf32-rounded
__device__ float g_Wt   [25*DM*DM];                // [tap][o][c], tf32-rounded
__device__ float g_kern [HH*TCH];
__device__ float g_E    [HH*TCH*NST*2];
__device__ float g_P    [HH*TCH*NST*2];
__device__ float g_lamT [HH*NST*2];
__device__ float g_S    [(size_t)BATCH*HH*NC*NST*2];   // [bh][c][64nri]
__device__ float g_Pm   [(size_t)HH*TCH*TCH];
__device__ float g_Tm   [(size_t)HH*TCH*TCH];
__device__ float g_Dm   [(size_t)HH*TCH*TCH];

__device__ __forceinline__ unsigned f2tf(float f) {
    unsigned u; asm("cvt.rna.tf32.f32 %0, %1;" : "=r"(u) : "f"(f)); return u;
}
__device__ __forceinline__ void mma_tf32(float c[4], const unsigned a[4], const unsigned b[2]) {
    asm volatile("mma.sync.aligned.m16n8k8.row.col.f32.tf32.tf32.f32 "
        "{%0,%1,%2,%3}, {%4,%5,%6,%7}, {%8,%9}, {%0,%1,%2,%3};"
        : "+f"(c[0]), "+f"(c[1]), "+f"(c[2]), "+f"(c[3])
        : "r"(a[0]), "r"(a[1]), "r"(a[2]), "r"(a[3]), "r"(b[0]), "r"(b[1]));
}

// ---------------- K0a: x -> g_xp (tf32-rounded) ----------------
__global__ void k_xp(const float* __restrict__ x) {
    size_t i = (size_t)blockIdx.x*256 + threadIdx.x;
    g_xp[i] = __uint_as_float(f2tf(x[i]));
}
// ---------------- K0b: gate/res weights -> g_Wp ----------------
__global__ void k_wp(const float* __restrict__ gw, const float* __restrict__ rw) {
    int o = blockIdx.x, c = threadIdx.x;
    float v = (o < HH) ? gw[(size_t)o*DM + c] : rw[(size_t)(o-HH)*DM + c];
    g_Wp[(size_t)o*DM + c] = __uint_as_float(f2tf(v));
}
// ---------------- K0c: conv weights -> [tap][o][c], tf32 ----------------
__global__ void k_wt(const float* __restrict__ w0, const float* __restrict__ w1,
                     const float* __restrict__ w2) {
    int idx = blockIdx.x * 256 + threadIdx.x;       // tap<<16 | o<<8 | c
    int c = idx & 255, o = (idx >> 8) & 255, tap = idx >> 16;
    const float* w; int k, K;
    if (tap < 3)       { w = w0; k = tap;      K = 3;  }
    else if (tap < 10) { w = w1; k = tap - 3;  K = 7;  }
    else               { w = w2; k = tap - 10; K = 15; }
    g_Wt[idx] = __uint_as_float(f2tf(w[(o * DM + c) * K + k]));
}

// ---------------- K0d: S4D parameter tables ----------------
__global__ void k_s4prep(const float* __restrict__ log_dt, const float* __restrict__ A_re,
                         const float* __restrict__ A_im,  const float* __restrict__ C_re,
                         const float* __restrict__ C_im) {
    int h = blockIdx.x, n = threadIdx.x;
    float dt  = expf(log_dt[h]);
    float ar  = A_re[h*NST+n], ai = A_im[h*NST+n];
    float dar = dt*ar, dai = dt*ai;
    float er  = expf(dar);
    float lr  = er*cosf(dai), li = er*sinf(dai);
    float nr  = lr - 1.f, ni = li;
    float cr  = C_re[h*NST+n], ci = C_im[h*NST+n];
    float t1r = cr*nr - ci*ni, t1i = cr*ni + ci*nr;
    float den = ar*ar + ai*ai;
    float cdr = (t1r*ar + t1i*ai)/den;
    float cdi = (t1i*ar - t1r*ai)/den;

    float pr = cdr, pi = cdi;
    for (int t = 0; t < TCH; t++) {
        float s = pr;
        #pragma unroll
        for (int off = 16; off; off >>= 1) s += __shfl_xor_sync(0xffffffffu, s, off);
        if (n == 0) g_kern[h*TCH + t] = 2.f*s;
        float npr = pr*lr - pi*li, npi = pr*li + pi*lr;
        pr = npr; pi = npi;
        g_E[((h*TCH + t)*NST + n)*2 + 0] = pr;
        g_E[((h*TCH + t)*NST + n)*2 + 1] = pi;
    }
    float qr = 1.f, qi = 0.f;
    for (int m = 0; m < TCH; m++) {
        g_P[((h*TCH + (TCH-1-m))*NST + n)*2 + 0] = qr;
        g_P[((h*TCH + (TCH-1-m))*NST + n)*2 + 1] = qi;
        float nqr = qr*lr - qi*li, nqi = qr*li + qi*lr;
        qr = nqr; qi = nqi;
    }
    g_lamT[(h*NST+n)*2+0] = qr;
    g_lamT[(h*NST+n)*2+1] = qi;
}

// ---------------- K0e: GEMM-layout tables Pm/Tm/Dm ----------------
__global__ void k_tables(const float* __restrict__ Dskip) {
    int h = blockIdx.x;
    float dsk = Dskip[h];
    for (int i = threadIdx.x; i < TCH*TCH; i += 256) {
        int nri = i >> 6, t = i & 63;
        int n = nri >> 1, ri = nri & 1;
        g_Pm[(size_t)h*4096 + i] = __uint_as_float(f2tf(g_P[((h*TCH + t)*NST + n)*2 + ri]));
        int to = i >> 6, nri2 = i & 63;
        int n2 = nri2 >> 1, ri2 = nri2 & 1;
        float e = g_E[((h*TCH + to)*NST + n2)*2 + ri2];
        g_Dm[(size_t)h*4096 + i] = __uint_as_float(f2tf(ri2 ? -2.f*e : 2.f*e));
        int ti = i & 63;
        float v = 0.f;
        if (to >= ti) { v = g_kern[h*TCH + (to - ti)]; if (to == ti) v += dsk; }
        g_Tm[(size_t)h*4096 + i] = __uint_as_float(f2tf(v));
    }
}

// ---------------- K1: gate + res projections via tf32 mma (R8 structure, verbatim staging) ----------------
__global__ __launch_bounds__(256, 2) void k_gemm(const float* __restrict__ gb,
                                                 const float* __restrict__ rb) {
    extern __shared__ unsigned sm[];
    unsigned* Xs = sm;              // [128][68]
    unsigned* Ws = sm + 128*68;     // [128][68]
    int row0 = blockIdx.x * 128;
    int col0 = blockIdx.y * 128;
    int z    = blockIdx.z;
    const unsigned* Xp = (const unsigned*)g_xp;
    const unsigned* Wp = (const unsigned*)g_Wp + (z ? (size_t)HH*DM : 0);
    const float* Bv = z ? rb : gb;
    int tid = threadIdx.x, lane = tid & 31, wp = tid >> 5;
    int mw = (wp & 3) * 32, nw = (wp >> 2) * 64;
    int r_lo = lane >> 2, tg = lane & 3;
    float acc[2][8][4] = {};
    for (int c0 = 0; c0 < DM; c0 += 64) {
        __syncthreads();
        #pragma unroll
        for (int i = 0; i < 8; i++) {
            int lin = i*256 + tid; int r = lin >> 4, q = lin & 15;
            *(uint4*)(Xs + r*68 + 4*q) = *(const uint4*)(Xp + (size_t)(row0 + r)*DM + c0 + 4*q);
        }
        #pragma unroll
        for (int i = 0; i < 8; i++) {
            int lin = i*256 + tid; int r = lin >> 4, q = lin & 15;
            *(uint4*)(Ws + r*68 + 4*q) = *(const uint4*)(Wp + (size_t)(col0 + r)*DM + c0 + 4*q);
        }
        __syncthreads();
        #pragma unroll
        for (int kk = 0; kk < 64; kk += 8) {
            unsigned a[2][4], b[8][2];
            #pragma unroll
            for (int mt = 0; mt < 2; mt++) {
                int base = (mw + mt*16 + r_lo)*68 + kk + tg;
                a[mt][0] = Xs[base];       a[mt][1] = Xs[base + 8*68];
                a[mt][2] = Xs[base + 4];   a[mt][3] = Xs[base + 8*68 + 4];
            }
            #pragma unroll
            for (int nt = 0; nt < 8; nt++) {
                int bb = (nw + nt*8 + r_lo)*68 + kk + tg;
                b[nt][0] = Ws[bb]; b[nt][1] = Ws[bb + 4];
            }
            #pragma unroll
            for (int mt = 0; mt < 2; mt++)
                #pragma unroll
                for (int nt = 0; nt < 8; nt++)
                    mma_tf32(acc[mt][nt], a[mt], b[nt]);
        }
    }
    if (z == 1) {
        #pragma unroll
        for (int mt = 0; mt < 2; mt++)
            #pragma unroll
            for (int nt = 0; nt < 8; nt++)
                #pragma unroll
                for (int rr = 0; rr < 2; rr++) {
                    int row = row0 + mw + mt*16 + r_lo + rr*8;
                    int col = col0 + nw + nt*8 + 2*tg;
                    float2 v = make_float2(acc[mt][nt][rr*2+0] + Bv[col],
                                           acc[mt][nt][rr*2+1] + Bv[col+1]);
                    *(float2*)(g_resid + (size_t)row*HH + col) = v;
                }
    } else {
        __syncthreads();
        float* tile = (float*)sm;   // [128 h][132 l]
        #pragma unroll
        for (int mt = 0; mt < 2; mt++)
            #pragma unroll
            for (int nt = 0; nt < 8; nt++)
                #pragma unroll
                for (int rr = 0; rr < 2; rr++) {
                    int m = mw + mt*16 + r_lo + rr*8;
                    int n = nw + nt*8 + 2*tg;
                    float v0 = acc[mt][nt][rr*2+0] + Bv[col0+n];
                    float v1 = acc[mt][nt][rr*2+1] + Bv[col0+n+1];
                    tile[n*132 + m]     = 1.f/(1.f + __expf(-v0));
                    tile[(n+1)*132 + m] = 1.f/(1.f + __expf(-v1));
                }
        __syncthreads();
        int b = row0 / SEQL, l0 = row0 % SEQL;
        int hh = tid >> 1, l_off = (tid & 1) * 64;
        float* dst = g_gate + ((size_t)(b*HH) + col0 + hh)*SEQL + l0 + l_off;
        #pragma unroll
        for (int q = 0; q < 16; q++)
            *(float4*)(dst + 4*q) = *(float4*)(tile + hh*132 + l_off + 4*q);
    }
}

// ---------------- K2: dilated convs via tf32 mma (R8 structure, verbatim staging) ----------------
__global__ __launch_bounds__(256, 2) void k_conv(const float* __restrict__ cb0,
        const float* __restrict__ cb1, const float* __restrict__ cb2) {
    extern __shared__ unsigned sm[];
    unsigned* Us = sm;                // [184][68]
    unsigned* Ws = sm + 184*68;       // [128 o][68 c]
    int br   = blockIdx.y >> 1;
    int o0   = (blockIdx.y & 1) * 128;
    int K, dil, tb; const float* cb;
    if (br == 0)      { K = 3;  dil = 1; tb = 0;  cb = cb0; }
    else if (br == 1) { K = 7;  dil = 2; tb = 3;  cb = cb1; }
    else              { K = 15; dil = 4; tb = 10; cb = cb2; }
    int l0 = blockIdx.x * 128;
    int b  = blockIdx.z;
    int tid = threadIdx.x, lane = tid & 31, wp = tid >> 5;
    int mw = (wp & 3) * 32, nw = (wp >> 2) * 64;
    int r_lo = lane >> 2, tg = lane & 3;
    float acc[2][8][4] = {};
    const unsigned* Xp  = (const unsigned*)g_xp;
    const unsigned* Wtu = (const unsigned*)g_Wt;
    for (int c0 = 0; c0 < DM; c0 += 64) {
        __syncthreads();
        #pragma unroll
        for (int i = 0; i < 12; i++) {
            int lin = i*256 + tid;
            if (lin < 2944) {
                int r = lin >> 4, q = lin & 15;
                int l = l0 - 28 + r;
                uint4 t = make_uint4(0u, 0u, 0u, 0u);
                if ((unsigned)l < SEQL)
                    t = *(const uint4*)(Xp + ((size_t)(b*SEQL + l))*DM + c0 + 4*q);
                *(uint4*)(Us + r*68 + 4*q) = t;
            }
        }
        for (int k = 0; k < K; k++) {
            __syncthreads();
            #pragma unroll
            for (int i = 0; i < 8; i++) {
                int lin = i*256 + tid; int r = lin >> 4, q = lin & 15;
                *(uint4*)(Ws + r*68 + 4*q) =
                    *(const uint4*)(Wtu + (size_t)(tb + k)*65536 + (o0 + r)*256 + c0 + 4*q);
            }
            __syncthreads();
            int lb = 28 + (k - K/2) * dil;
            #pragma unroll
            for (int kk = 0; kk < 64; kk += 8) {
                unsigned a[2][4], bfr[8][2];
                #pragma unroll
                for (int mt = 0; mt < 2; mt++) {
                    int base = (lb + mw + mt*16 + r_lo)*68 + kk + tg;
                    a[mt][0] = Us[base];       a[mt][1] = Us[base + 8*68];
                    a[mt][2] = Us[base + 4];   a[mt][3] = Us[base + 8*68 + 4];
                }
                #pragma unroll
                for (int nt = 0; nt < 8; nt++) {
                    int bb = (nw + nt*8 + r_lo)*68 + kk + tg;
                    bfr[nt][0] = Ws[bb]; bfr[nt][1] = Ws[bb + 4];
                }
                #pragma unroll
                for (int mt = 0; mt < 2; mt++)
                    #pragma unroll
                    for (int nt = 0; nt < 8; nt++)
                        mma_tf32(acc[mt][nt], a[mt], bfr[nt]);
            }
        }
    }
    __syncthreads();
    float* tile = (float*)sm;   // [128 o][132 l]
    #pragma unroll
    for (int mt = 0; mt < 2; mt++)
        #pragma unroll
        for (int nt = 0; nt < 8; nt++)
            #pragma unroll
            for (int rr = 0; rr < 2; rr++) {
                int m = mw + mt*16 + r_lo + rr*8;
                int n = nw + nt*8 + 2*tg;
                tile[n*132 + m]     = acc[mt][nt][rr*2+0];
                tile[(n+1)*132 + m] = acc[mt][nt][rr*2+1];
            }
    __syncthreads();
    int hh = tid >> 1, l_off = (tid & 1) * 64;
    int hglob = br*256 + o0 + hh;
    float bias = cb[o0 + hh];
    const float* gp = g_gate  + ((size_t)(b*HH) + hglob)*SEQL + l0 + l_off;
    float*       op = g_gated + ((size_t)(b*HH) + hglob)*SEQL + l0 + l_off;
    #pragma unroll
    for (int q = 0; q < 16; q++) {
        float4 a = *(float4*)(tile + hh*132 + l_off + 4*q);
        float4 g = *(const float4*)(gp + 4*q);
        *(float4*)(op + 4*q) = make_float4((a.x+bias)*g.x, (a.y+bias)*g.y,
                                           (a.z+bias)*g.z, (a.w+bias)*g.w);
    }
}

// ---------------- 64x64x64 tf32 GEMM helpers ----------------
__device__ __forceinline__ void load_tile_tf32(unsigned* dst, const float* src, int tid) {
    const float4* p = (const float4*)src;
    #pragma unroll
    for (int i = 0; i < 8; i++) {
        int lin = i*128 + tid; int r = lin >> 4, q = lin & 15;
        float4 v = p[lin];
        *(uint4*)(dst + r*68 + 4*q) = make_uint4(f2tf(v.x), f2tf(v.y), f2tf(v.z), f2tf(v.w));
    }
}
__device__ __forceinline__ void load_tile_raw(unsigned* dst, const unsigned* src, int tid) {
    const uint4* p = (const uint4*)src;
    #pragma unroll
    for (int i = 0; i < 8; i++) {
        int lin = i*128 + tid; int r = lin >> 4, q = lin & 15;
        *(uint4*)(dst + r*68 + 4*q) = p[lin];
    }
}
__device__ __forceinline__ void gemm64(float acc[8][4], const unsigned* As, const unsigned* Bs,
                                       int m0, int r_lo, int tg) {
    #pragma unroll
    for (int kk = 0; kk < 64; kk += 8) {
        unsigned a[4];
        int base = (m0 + r_lo)*68 + kk + tg;
        a[0] = As[base];       a[1] = As[base + 8*68];
        a[2] = As[base + 4];   a[3] = As[base + 8*68 + 4];
        #pragma unroll
        for (int nt = 0; nt < 8; nt++) {
            unsigned b[2]; int bb = (nt*8 + r_lo)*68 + kk + tg;
            b[0] = Bs[bb]; b[1] = Bs[bb + 4];
            mma_tf32(acc[nt], a, b);
        }
    }
}

// ---------------- K3: encode + in-block cross-chunk scan -> g_S ----------------
__global__ __launch_bounds__(128) void k_enc(void) {
    __shared__ unsigned Us[64*68], Ps[64*68];
    int bh = blockIdx.x, h = bh % HH, tid = threadIdx.x;
    load_tile_tf32(Us, g_gated + (size_t)bh*SEQL, tid);
    load_tile_raw (Ps, (const unsigned*)g_Pm + (size_t)h*4096, tid);
    __syncthreads();
    int lane = tid & 31, wp = tid >> 5, m0 = wp*16, r_lo = lane >> 2, tg = lane & 3;
    float acc[8][4] = {};
    gemm64(acc, Us, Ps, m0, r_lo, tg);
    __syncthreads();                       // all warps done reading Ps
    float* Fs = (float*)Ps;                // reuse as F[64 chunks][64 nri]
    #pragma unroll
    for (int nt = 0; nt < 8; nt++) {
        int col = nt*8 + 2*tg;
        Fs[(m0 + r_lo)*64 + col]       = acc[nt][0];
        Fs[(m0 + r_lo)*64 + col + 1]   = acc[nt][1];
        Fs[(m0 + r_lo + 8)*64 + col]   = acc[nt][2];
        Fs[(m0 + r_lo + 8)*64 + col+1] = acc[nt][3];
    }
    __syncthreads();
    if (tid < 32) {                        // warp 0: sequential scan over 64 chunks
        int n = tid;
        float2 lam = ((const float2*)g_lamT)[h*NST + n];
        float sr = 0.f, si = 0.f;
        float2* S2 = (float2*)(g_S + (size_t)bh*4096);
        for (int c = 0; c < NC; c++) {
            S2[c*32 + n] = make_float2(sr, si);
            float2 f = *(float2*)(Fs + c*64 + 2*n);
            float nsr = sr*lam.x - si*lam.y + f.x;
            float nsi = sr*lam.y + si*lam.x + f.y;
            sr = nsr; si = nsi;
        }
    }
}

// ---------------- K5: decode Y = U*Tm^T + S*Dm^T -> g_ys4 ----------------
__global__ __launch_bounds__(128) void k_dec(void) {
    __shared__ unsigned As[64*68], Bs[64*68];
    int bh = blockIdx.x, h = bh % HH, tid = threadIdx.x;
    load_tile_tf32(As, g_gated + (size_t)bh*SEQL, tid);
    load_tile_raw (Bs, (const unsigned*)g_Tm + (size_t)h*4096, tid);
    __syncthreads();
    int lane = tid & 31, wp = tid >> 5, m0 = wp*16, r_lo = lane >> 2, tg = lane & 3;
    float acc[8][4] = {};
    gemm64(acc, As, Bs, m0, r_lo, tg);
    __syncthreads();
    load_tile_tf32(As, g_S + (size_t)bh*4096, tid);
    load_tile_raw (Bs, (const unsigned*)g_Dm + (size_t)h*4096, tid);
    __syncthreads();
    gemm64(acc, As, Bs, m0, r_lo, tg);
    #pragma unroll
    for (int nt = 0; nt < 8; nt++) {
        int col = nt*8 + 2*tg;
        float* f = g_ys4 + (size_t)bh*SEQL + (m0 + r_lo)*64 + col;
        *(float2*)f         = make_float2(acc[nt][0], acc[nt][1]);
        *(float2*)(f + 512) = make_float2(acc[nt][2], acc[nt][3]);
    }
}

// ---------------- K6: transpose + residual + LayerNorm ----------------
__global__ __launch_bounds__(256) void k_ln(const float* __restrict__ gamma,
                                            const float* __restrict__ beta,
                                            float* __restrict__ out) {
    __shared__ float tile[16][768];
    int b  = blockIdx.y;
    int l0 = blockIdx.x * 16;
    for (int hh = threadIdx.x; hh < HH; hh += 256) {
        const float4* p = (const float4*)(g_ys4 + ((size_t)(b*HH + hh))*SEQL + l0);
        #pragma unroll
        for (int q = 0; q < 4; q++) {
            float4 v = p[q];
            tile[4*q+0][hh] = v.x; tile[4*q+1][hh] = v.y;
            tile[4*q+2][hh] = v.z; tile[4*q+3][hh] = v.w;
        }
    }
    __syncthreads();
    int w = threadIdx.x >> 5, lane = threadIdx.x & 31;
    #pragma unroll
    for (int rr = 0; rr < 2; rr++) {
        int j = w + rr*8;
        int l = l0 + j;
        size_t rbase = ((size_t)(b*SEQL + l))*HH;
        float s = 0.f, s2 = 0.f;
        for (int hh = lane; hh < HH; hh += 32) {
            float y = tile[j][hh] + g_resid[rbase + hh];
            tile[j][hh] = y;
            s += y; s2 += y*y;
        }
        #pragma unroll
        for (int off = 16; off; off >>= 1) {
            s  += __shfl_xor_sync(0xffffffffu, s,  off);
            s2 += __shfl_xor_sync(0xffffffffu, s2, off);
        }
        float mu   = s * (1.f/HH);
        float var  = s2 * (1.f/HH) - mu*mu;
        float rstd = rsqrtf(var + 1e-5f);
        for (int hh = lane; hh < HH; hh += 32) {
            out[rbase + hh] = (tile[j][hh] - mu) * rstd * gamma[hh] + beta[hh];
        }
    }
}

extern "C" void kernel_launch(void* const* d_in, const int* in_sizes, int n_in,
                              void* d_out, int out_size) {
    const float* x      = (const float*)d_in[0];
    const float* cw0    = (const float*)d_in[1];
    const float* cb0    = (const float*)d_in[2];
    const float* cw1    = (const float*)d_in[3];
    const float* cb1    = (const float*)d_in[4];
    const float* cw2    = (const float*)d_in[5];
    const float* cb2    = (const float*)d_in[6];
    const float* gw     = (const float*)d_in[7];
    const float* gb     = (const float*)d_in[8];
    const float* rw     = (const float*)d_in[9];
    const float* rb     = (const float*)d_in[10];
    const float* log_dt = (const float*)d_in[11];
    const float* A_re   = (const float*)d_in[12];
    const float* A_im   = (const float*)d_in[13];
    const float* C_re   = (const float*)d_in[14];
    const float* C_im   = (const float*)d_in[15];
    const float* Dskip  = (const float*)d_in[16];
    const float* lng    = (const float*)d_in[17];
    const float* lnb    = (const float*)d_in[18];
    float* out = (float*)d_out;

    const int GEMM_SMEM = 2 * 128 * 68 * 4;          // 69632 B -> 2 CTA/SM
    const int CONV_SMEM = (184*68 + 128*68) * 4;     // 84864 B -> 2 CTA/SM
    cudaFuncSetAttribute(k_gemm, cudaFuncAttributeMaxDynamicSharedMemorySize, GEMM_SMEM);
    cudaFuncSetAttribute(k_conv, cudaFuncAttributeMaxDynamicSharedMemorySize, CONV_SMEM);

    k_xp<<<(BATCH*SEQL*DM)/256, 256>>>(x);
    k_wp<<<2*HH, 256>>>(gw, rw);
    k_wt<<<25*256, 256>>>(cw0, cw1, cw2);
    k_s4prep<<<HH, NST>>>(log_dt, A_re, A_im, C_re, C_im);
    k_tables<<<HH, 256>>>(Dskip);
    k_gemm<<<dim3(256, 6, 2), 256, GEMM_SMEM>>>(gb, rb);
    k_conv<<<dim3(32, 6, 8), 256, CONV_SMEM>>>(cb0, cb1, cb2);
    k_enc<<<BATCH*HH, 128>>>();
    k_dec<<<BATCH*HH, 128>>>();
    k_ln<<<dim3(SEQL/16, BATCH), 256>>>(lng, lnb, out);
}